// round 5
// baseline (speedup 1.0000x reference)
#include <cuda_runtime.h>
#include <math.h>

#define NUM_Q   8
#define DIM     256
#define N_EMBED 1024
#define NROWS   65536
#define QOUT_ELEMS (NROWS * DIM)

#define TM 64
#define TN 64      // codes per ct tile
#define BK 32      // k-chunk
#define NTHREADS 256
#define ATS 68     // At row stride (floats): [DIM][ATS], 16B-aligned per d
#define BSD 136    // dup'd B row stride (floats): 128 dup'd + 8 pad

__device__ float g_res[NROWS * DIM];
__device__ float g_embT[NUM_Q * N_EMBED * DIM];
__device__ float g_norms[NUM_Q * N_EMBED];
__device__ float g_losspart[NUM_Q * (NROWS / TM)];
__device__ int   g_counts[NUM_Q * N_EMBED];

typedef unsigned long long ull;
__device__ __forceinline__ ull fma2(ull a, ull b, ull c) {
  ull d; asm("fma.rn.f32x2 %0, %1, %2, %3;" : "=l"(d) : "l"(a), "l"(b), "l"(c));
  return d;
}
__device__ __forceinline__ float2 unpack2(ull v) {
  float2 f; asm("mov.b64 {%0, %1}, %2;" : "=f"(f.x), "=f"(f.y) : "l"(v));
  return f;
}

// ---------------- prep: transpose codebooks (code-major) + zero counts ----------------
__global__ void prep_kernel(const float* __restrict__ embeds) {
  int idx = blockIdx.x * 256 + threadIdx.x;
  int l = idx >> 18;
  int rem = idx & 262143;
  int d = rem >> 10;
  int k = rem & 1023;
  g_embT[((size_t)l * N_EMBED + k) * DIM + d] = embeds[idx];
  if (idx < NUM_Q * N_EMBED) g_counts[idx] = 0;
}

// ---------------- code norms: sequential d, separate mul+add ----------------
__global__ void norms_kernel(const float* __restrict__ embeds) {
  int k = blockIdx.x * 256 + threadIdx.x;
  int l = k >> 10;
  int kk = k & 1023;
  float s = 0.f;
  for (int d = 0; d < DIM; ++d) {
    float v = embeds[((size_t)l * DIM + d) * N_EMBED + kk];
    s = __fadd_rn(s, __fmul_rn(v, v));
  }
  g_norms[k] = s;
}

// ---------------- main fused VQ layer ----------------
__global__ void __launch_bounds__(NTHREADS, 2)
vq_layer_kernel(const float* __restrict__ x,
                const float* __restrict__ embeds,
                float* __restrict__ qout,
                int layer) {
  extern __shared__ float sm[];
  float* At   = sm;                          // [DIM][ATS] transposed residual
  float* Bs   = sm + DIM * ATS;              // [2][BK][BSD] dup'd, double-buffered
  int*   sInd = (int*)(Bs + 2 * BK * BSD);   // [TM]
  float* sRN  = (float*)(sInd + TM);         // [TM]
  float* sRed = sRN + TM;                    // [8]

  const int tid = threadIdx.x;
  const int ty = tid >> 4;      // 0..15  rows ty*4..+3
  const int tx = tid & 15;      // 0..15  codes tx*4..+3 within tile
  const int wid = tid >> 5, lane = tid & 31;

  const float* resin = (layer == 0) ? x : g_res;
  const float* rbase = resin + (size_t)blockIdx.x * TM * DIM;

  // ---- ||r||^2 per row (same XLA pattern/bits as R3, reading global) ----
  #pragma unroll 1
  for (int rr = 0; rr < 8; ++rr) {
    int row = wid * 8 + rr;
    const float* rp = rbase + row * DIM;
    float p0 = 0.f, p1 = 0.f;
    #pragma unroll
    for (int i = 0; i < 4; ++i) {
      float2 v = __ldg((const float2*)&rp[i * 64 + 2 * lane]);
      p0 = __fadd_rn(p0, __fmul_rn(v.x, v.x));
      p1 = __fadd_rn(p1, __fmul_rn(v.y, v.y));
    }
    float a = __fadd_rn(p0, p1);
    #pragma unroll
    for (int off = 16; off > 0; off >>= 1)
      a = __fadd_rn(a, __shfl_down_sync(0xffffffff, a, off));
    if (lane == 0) sRN[row] = a;
  }

  // ---- scatter-store transposed residual: At[d][row] ----
  {
    const int row = tid & 63;            // lanes -> consecutive rows
    const int g0  = tid >> 6;            // d-group of 4
    const float* rp = rbase + row * DIM;
    #pragma unroll
    for (int g = 0; g < 16; ++g) {
      int gg = g0 + g * 4;
      float4 v = __ldg((const float4*)rp + gg);
      At[(gg * 4 + 0) * ATS + row] = v.x;
      At[(gg * 4 + 1) * ATS + row] = v.y;
      At[(gg * 4 + 2) * ATS + row] = v.z;
      At[(gg * 4 + 3) * ATS + row] = v.w;
    }
  }

  // ---- prologue: load B chunk (ct=0, kc=0) into buf0, dup'd ----
  const int brow = tid >> 3;          // 0..31 (k-row in chunk)
  const int bcol = (tid & 7) * 8;     // source float offset (8 per thread)
  {
    const float* g = embeds + ((size_t)(layer * DIM + brow)) * N_EMBED + bcol;
    float4 v0 = __ldg((const float4*)g);
    float4 v1 = __ldg((const float4*)g + 1);
    float* bd = Bs + brow * BSD + bcol * 2;
    *(float4*)(bd + 0)  = make_float4(v0.x, v0.x, v0.y, v0.y);
    *(float4*)(bd + 4)  = make_float4(v0.z, v0.z, v0.w, v0.w);
    *(float4*)(bd + 8)  = make_float4(v1.x, v1.x, v1.y, v1.y);
    *(float4*)(bd + 12) = make_float4(v1.z, v1.z, v1.w, v1.w);
  }
  __syncthreads();

  float bestv[4];
  int   besti[4];
  #pragma unroll
  for (int i = 0; i < 4; ++i) { bestv[i] = 3.4028235e38f; besti[i] = 0; }

  for (int ct = 0; ct < N_EMBED / TN; ++ct) {
    // acc[pair][code]: pair0 = rows (ty*4, ty*4+1), pair1 = rows (ty*4+2, ty*4+3)
    ull acc[2][4];
    #pragma unroll
    for (int j = 0; j < 4; ++j) { acc[0][j] = 0ull; acc[1][j] = 0ull; }

    for (int kc = 0; kc < DIM / BK; ++kc) {
      const int idx = ct * 8 + kc;
      const int p = idx & 1;

      // prefetch next B chunk into registers
      float4 nv0, nv1;
      const bool have = (idx + 1) < 128;
      if (have) {
        int nidx = idx + 1;
        int nct = nidx >> 3, nkc = nidx & 7;
        const float* g = embeds + ((size_t)(layer * DIM + nkc * BK + brow)) * N_EMBED
                         + nct * TN + bcol;
        nv0 = __ldg((const float4*)g);
        nv1 = __ldg((const float4*)g + 1);
      }

      // compute on buffer p
      const float* bp = Bs + p * (BK * BSD) + tx * 8;
      const float* ap = At + (kc * BK) * ATS + ty * 4;
      #pragma unroll
      for (int d = 0; d < BK; ++d) {
        ulonglong2 a   = *(const ulonglong2*)(ap + d * ATS);
        ulonglong2 b01 = *(const ulonglong2*)(bp + d * BSD);
        ulonglong2 b23 = *(const ulonglong2*)(bp + d * BSD + 4);
        acc[0][0] = fma2(a.x, b01.x, acc[0][0]);
        acc[0][1] = fma2(a.x, b01.y, acc[0][1]);
        acc[0][2] = fma2(a.x, b23.x, acc[0][2]);
        acc[0][3] = fma2(a.x, b23.y, acc[0][3]);
        acc[1][0] = fma2(a.y, b01.x, acc[1][0]);
        acc[1][1] = fma2(a.y, b01.y, acc[1][1]);
        acc[1][2] = fma2(a.y, b23.x, acc[1][2]);
        acc[1][3] = fma2(a.y, b23.y, acc[1][3]);
      }

      // store prefetched chunk into the other buffer (safe: last read 2 iters ago)
      if (have) {
        float* bd = Bs + (p ^ 1) * (BK * BSD) + brow * BSD + bcol * 2;
        *(float4*)(bd + 0)  = make_float4(nv0.x, nv0.x, nv0.y, nv0.y);
        *(float4*)(bd + 4)  = make_float4(nv0.z, nv0.z, nv0.w, nv0.w);
        *(float4*)(bd + 8)  = make_float4(nv1.x, nv1.x, nv1.y, nv1.y);
        *(float4*)(bd + 12) = make_float4(nv1.z, nv1.z, nv1.w, nv1.w);
      }
      __syncthreads();
    }

    // dist = (rn - 2*ab) + en, exact association, ascending code order per row
    #pragma unroll
    for (int pr = 0; pr < 2; ++pr) {
      float rn0 = sRN[ty * 4 + pr * 2];
      float rn1 = sRN[ty * 4 + pr * 2 + 1];
      #pragma unroll
      for (int j = 0; j < 4; ++j) {
        float2 s = unpack2(acc[pr][j]);
        int code = ct * TN + tx * 4 + j;
        float en = __ldg(&g_norms[layer * N_EMBED + code]);
        float d0 = __fadd_rn(__fadd_rn(rn0, __fmul_rn(-2.0f, s.x)), en);
        float d1 = __fadd_rn(__fadd_rn(rn1, __fmul_rn(-2.0f, s.y)), en);
        int b0 = pr * 2, b1 = pr * 2 + 1;
        if (d0 < bestv[b0]) { bestv[b0] = d0; besti[b0] = code; }
        if (d1 < bestv[b1]) { bestv[b1] = d1; besti[b1] = code; }
      }
    }
  }

  // argmin across the 16 tx lanes, lowest-index tie-break
  #pragma unroll
  for (int off = 1; off < 16; off <<= 1) {
    #pragma unroll
    for (int i = 0; i < 4; ++i) {
      float ov = __shfl_xor_sync(0xffffffff, bestv[i], off);
      int   oi = __shfl_xor_sync(0xffffffff, besti[i], off);
      if (ov < bestv[i] || (ov == bestv[i] && oi < besti[i])) {
        bestv[i] = ov; besti[i] = oi;
      }
    }
  }
  if (tx == 0) {
    #pragma unroll
    for (int i = 0; i < 4; ++i) sInd[ty * 4 + i] = besti[i];
  }
  __syncthreads();

  // ------------- epilogue: exact straight-through chain (residual from global) -------------
  float lsum = 0.f;
  const size_t rowbase = (size_t)blockIdx.x * TM;

  #pragma unroll 1
  for (int rr = 0; rr < 8; ++rr) {
    int r = wid * 8 + rr;
    int c = sInd[r];
    const float* q   = g_embT + ((size_t)layer * N_EMBED + c) * DIM;
    float* outp      = qout  + (rowbase + r) * DIM;
    float* resp      = g_res + (rowbase + r) * DIM;
    const float* rsm = rbase + r * DIM;
    #pragma unroll
    for (int h = 0; h < 2; ++h) {
      int d = lane * 4 + h * 128;
      float4 qv = __ldg((const float4*)(q + d));
      float4 rv = __ldg((const float4*)(rsm + d));
      float4 dq, qst, nr;
      dq.x = __fadd_rn(qv.x, -rv.x); dq.y = __fadd_rn(qv.y, -rv.y);
      dq.z = __fadd_rn(qv.z, -rv.z); dq.w = __fadd_rn(qv.w, -rv.w);
      qst.x = __fadd_rn(rv.x, dq.x); qst.y = __fadd_rn(rv.y, dq.y);
      qst.z = __fadd_rn(rv.z, dq.z); qst.w = __fadd_rn(rv.w, dq.w);
      nr.x = __fadd_rn(rv.x, -qst.x); nr.y = __fadd_rn(rv.y, -qst.y);
      nr.z = __fadd_rn(rv.z, -qst.z); nr.w = __fadd_rn(rv.w, -qst.w);
      *(float4*)(resp + d) = nr;
      float4 ov;
      if (layer == 0) {
        ov = qst;
      } else {
        ov = *(const float4*)(outp + d);
        ov.x = __fadd_rn(ov.x, qst.x); ov.y = __fadd_rn(ov.y, qst.y);
        ov.z = __fadd_rn(ov.z, qst.z); ov.w = __fadd_rn(ov.w, qst.w);
      }
      *(float4*)(outp + d) = ov;
      lsum += __fmul_rn(dq.x, dq.x) + __fmul_rn(dq.y, dq.y)
            + __fmul_rn(dq.z, dq.z) + __fmul_rn(dq.w, dq.w);
    }
    if (lane == 0) atomicAdd(&g_counts[layer * N_EMBED + c], 1);
  }

  #pragma unroll
  for (int off = 16; off > 0; off >>= 1)
    lsum += __shfl_xor_sync(0xffffffff, lsum, off);
  if (lane == 0) sRed[wid] = lsum;
  __syncthreads();
  if (tid == 0) {
    float s = 0.f;
    #pragma unroll
    for (int w = 0; w < 8; ++w) s += sRed[w];
    g_losspart[layer * (NROWS / TM) + blockIdx.x] = s;
  }
}

// ---------------- finalize: loss mean + perplexity ----------------
__global__ void finalize_kernel(float* __restrict__ out) {
  const int l = blockIdx.x;
  const int tid = threadIdx.x;
  __shared__ double sd[256];
  __shared__ float  sf[256];
  double ls = 0.0;
  float  es = 0.f;
  for (int i = tid; i < NROWS / TM; i += 256)
    ls += (double)g_losspart[l * (NROWS / TM) + i];
  for (int i = tid; i < N_EMBED; i += 256) {
    float p = (float)g_counts[l * N_EMBED + i] * (1.0f / (float)NROWS);
    es += p * logf(__fadd_rn(p, 1e-10f));
  }
  sd[tid] = ls; sf[tid] = es;
  __syncthreads();
  for (int s = 128; s > 0; s >>= 1) {
    if (tid < s) { sd[tid] += sd[tid + s]; sf[tid] += sf[tid + s]; }
    __syncthreads();
  }
  if (tid == 0) {
    out[QOUT_ELEMS + l]         = (float)(sd[0] / (double)QOUT_ELEMS);
    out[QOUT_ELEMS + NUM_Q + l] = expf(-sf[0]);
  }
}

extern "C" void kernel_launch(void* const* d_in, const int* in_sizes, int n_in,
                              void* d_out, int out_size) {
  const float* x      = (const float*)d_in[0];
  const float* embeds = (const float*)d_in[1];
  float* out          = (float*)d_out;

  const int smem_bytes = (DIM * ATS + 2 * BK * BSD + TM + TM + 8) * 4;
  cudaFuncSetAttribute(vq_layer_kernel,
                       cudaFuncAttributeMaxDynamicSharedMemorySize, smem_bytes);

  prep_kernel<<<(NUM_Q * N_EMBED * DIM) / 256, 256>>>(embeds);
  norms_kernel<<<(NUM_Q * N_EMBED) / 256, 256>>>(embeds);

  for (int l = 0; l < NUM_Q; ++l) {
    vq_layer_kernel<<<NROWS / TM, NTHREADS, smem_bytes>>>(x, embeds, out, l);
  }
  finalize_kernel<<<NUM_Q, 256>>>(out);
}

// round 6
// speedup vs baseline: 2.7848x; 2.7848x over previous
#include <cuda_runtime.h>
#include <math.h>

#define NUM_Q   8
#define DIM     256
#define N_EMBED 1024
#define NROWS   65536
#define QOUT_ELEMS (NROWS * DIM)

#define TM 64       // rows per block
#define TNC 128     // codes per ct tile
#define BK 32       // k-chunk
#define NTHREADS 256
#define ATS 68      // At row stride (floats)
#define BSROW 132   // Bs row stride (floats): 128 + 4 pad

__device__ float g_res[NROWS * DIM];
__device__ float g_embT[NUM_Q * N_EMBED * DIM];
__device__ float g_norms[NUM_Q * N_EMBED];
__device__ float g_losspart[NUM_Q * (NROWS / TM)];
__device__ int   g_counts[NUM_Q * N_EMBED];

typedef unsigned long long ull;
__device__ __forceinline__ ull fma2(ull a, ull b, ull c) {
  ull d; asm("fma.rn.f32x2 %0, %1, %2, %3;" : "=l"(d) : "l"(a), "l"(b), "l"(c));
  return d;
}
__device__ __forceinline__ ull packdup(float x) {
  ull r; asm("mov.b64 %0, {%1, %1};" : "=l"(r) : "f"(x));
  return r;
}
__device__ __forceinline__ float2 unpack2(ull v) {
  float2 f; asm("mov.b64 {%0, %1}, %2;" : "=f"(f.x), "=f"(f.y) : "l"(v));
  return f;
}

// ---------------- prep: transpose codebooks (code-major) + zero counts ----------------
__global__ void prep_kernel(const float* __restrict__ embeds) {
  int idx = blockIdx.x * 256 + threadIdx.x;
  int l = idx >> 18;
  int rem = idx & 262143;
  int d = rem >> 10;
  int k = rem & 1023;
  g_embT[((size_t)l * N_EMBED + k) * DIM + d] = embeds[idx];
  if (idx < NUM_Q * N_EMBED) g_counts[idx] = 0;
}

// ---------------- code norms: sequential d, separate mul+add ----------------
__global__ void norms_kernel(const float* __restrict__ embeds) {
  int k = blockIdx.x * 256 + threadIdx.x;
  int l = k >> 10;
  int kk = k & 1023;
  float s = 0.f;
  for (int d = 0; d < DIM; ++d) {
    float v = embeds[((size_t)l * DIM + d) * N_EMBED + kk];
    s = __fadd_rn(s, __fmul_rn(v, v));
  }
  g_norms[k] = s;
}

// ---------------- main fused VQ layer ----------------
__global__ void __launch_bounds__(NTHREADS, 2)
vq_layer_kernel(const float* __restrict__ x,
                const float* __restrict__ embeds,
                float* __restrict__ qout,
                int layer) {
  extern __shared__ float sm[];
  float* At    = sm;                           // [DIM][ATS] transposed residual
  float* Bs    = At + DIM * ATS;               // [BK][BSROW] plain B chunk
  float* sRN   = Bs + BK * BSROW;              // [TM]
  int*   sInd  = (int*)(sRN + TM);             // [TM]
  float* sRed  = (float*)(sInd + TM);          // [8]
  float* sArgV = sRed + 8;                     // [4][TM]
  int*   sArgI = (int*)(sArgV + 4 * TM);       // [4][TM]

  const int tid = threadIdx.x;
  const int wid = tid >> 5, lane = tid & 31;
  const int rhalf = wid & 1;            // row half (0/1)
  const int cq    = wid >> 1;           // code quarter (0..3)
  const int rg    = lane & 7;           // row group within half
  const int cg    = lane >> 3;          // code group within quarter
  const int rowsel  = rhalf * 32 + rg * 4;   // block-local first row
  const int codesel = cq * 32 + cg * 8;      // tile-local first code

  const float* resin = (layer == 0) ? x : g_res;
  const float* rbase = resin + (size_t)blockIdx.x * TM * DIM;

  // ---- ||r||^2 per row (XLA row-reduce pattern, from global) ----
  #pragma unroll 1
  for (int rr = 0; rr < 8; ++rr) {
    int row = wid * 8 + rr;
    const float* rp = rbase + row * DIM;
    float p0 = 0.f, p1 = 0.f;
    #pragma unroll
    for (int i = 0; i < 4; ++i) {
      float2 v = __ldg((const float2*)&rp[i * 64 + 2 * lane]);
      p0 = __fadd_rn(p0, __fmul_rn(v.x, v.x));
      p1 = __fadd_rn(p1, __fmul_rn(v.y, v.y));
    }
    float a = __fadd_rn(p0, p1);
    #pragma unroll
    for (int off = 16; off > 0; off >>= 1)
      a = __fadd_rn(a, __shfl_down_sync(0xffffffff, a, off));
    if (lane == 0) sRN[row] = a;
  }

  // ---- scatter-store transposed residual: At[d][row] ----
  {
    const int row = tid & 63;
    const int g0  = tid >> 6;
    const float* rp = rbase + row * DIM;
    #pragma unroll
    for (int g = 0; g < 16; ++g) {
      int gg = g0 + g * 4;
      float4 v = __ldg((const float4*)rp + gg);
      At[(gg * 4 + 0) * ATS + row] = v.x;
      At[(gg * 4 + 1) * ATS + row] = v.y;
      At[(gg * 4 + 2) * ATS + row] = v.z;
      At[(gg * 4 + 3) * ATS + row] = v.w;
    }
  }

  // B-fill assignment: thread loads 16 consecutive floats of one k-row
  const int brow = tid >> 3;          // 0..31
  const int bcol = (tid & 7) * 16;    // 0..112

  // prologue: prefetch chunk 0 (ct=0, kc=0) into regs
  float4 nv0, nv1, nv2, nv3;
  {
    const float* g = embeds + ((size_t)(layer * DIM + brow)) * N_EMBED + bcol;
    nv0 = __ldg((const float4*)g);
    nv1 = __ldg((const float4*)g + 1);
    nv2 = __ldg((const float4*)g + 2);
    nv3 = __ldg((const float4*)g + 3);
  }

  float bestv[4];
  int   besti[4];
  #pragma unroll
  for (int i = 0; i < 4; ++i) { bestv[i] = 3.4028235e38f; besti[i] = 0; }

  for (int ct = 0; ct < N_EMBED / TNC; ++ct) {
    ull acc[4][4];   // [row r][code pair jp]
    #pragma unroll
    for (int r = 0; r < 4; ++r)
      #pragma unroll
      for (int j = 0; j < 4; ++j) acc[r][j] = 0ull;

    for (int kc = 0; kc < DIM / BK; ++kc) {
      __syncthreads();   // previous chunk's compute done
      {
        float* bd = Bs + brow * BSROW + bcol;
        *(float4*)(bd + 0)  = nv0;
        *(float4*)(bd + 4)  = nv1;
        *(float4*)(bd + 8)  = nv2;
        *(float4*)(bd + 12) = nv3;
      }
      __syncthreads();   // Bs ready

      // prefetch next chunk
      int idx = ct * 8 + kc;
      if (idx + 1 < 64) {
        int nidx = idx + 1;
        int nct = nidx >> 3, nkc = nidx & 7;
        const float* g = embeds + ((size_t)(layer * DIM + nkc * BK + brow)) * N_EMBED
                         + nct * TNC + bcol;
        nv0 = __ldg((const float4*)g);
        nv1 = __ldg((const float4*)g + 1);
        nv2 = __ldg((const float4*)g + 2);
        nv3 = __ldg((const float4*)g + 3);
      }

      // compute: 32 k-steps
      const float* apd = At + (kc * BK) * ATS + rowsel;
      const float* bpd = Bs + codesel;
      #pragma unroll 8
      for (int d = 0; d < BK; ++d) {
        float4 a4 = *(const float4*)(apd + d * ATS);
        ulonglong2 b01 = *(const ulonglong2*)(bpd + d * BSROW);
        ulonglong2 b23 = *(const ulonglong2*)(bpd + d * BSROW + 4);
        ull ad0 = packdup(a4.x), ad1 = packdup(a4.y);
        ull ad2 = packdup(a4.z), ad3 = packdup(a4.w);
        acc[0][0] = fma2(ad0, b01.x, acc[0][0]);
        acc[0][1] = fma2(ad0, b01.y, acc[0][1]);
        acc[0][2] = fma2(ad0, b23.x, acc[0][2]);
        acc[0][3] = fma2(ad0, b23.y, acc[0][3]);
        acc[1][0] = fma2(ad1, b01.x, acc[1][0]);
        acc[1][1] = fma2(ad1, b01.y, acc[1][1]);
        acc[1][2] = fma2(ad1, b23.x, acc[1][2]);
        acc[1][3] = fma2(ad1, b23.y, acc[1][3]);
        acc[2][0] = fma2(ad2, b01.x, acc[2][0]);
        acc[2][1] = fma2(ad2, b01.y, acc[2][1]);
        acc[2][2] = fma2(ad2, b23.x, acc[2][2]);
        acc[2][3] = fma2(ad2, b23.y, acc[2][3]);
        acc[3][0] = fma2(ad3, b01.x, acc[3][0]);
        acc[3][1] = fma2(ad3, b01.y, acc[3][1]);
        acc[3][2] = fma2(ad3, b23.x, acc[3][2]);
        acc[3][3] = fma2(ad3, b23.y, acc[3][3]);
      }
    }

    // dist = (rn - 2*ab) + en, exact association, ascending code order
    const int cbase = ct * TNC + codesel;
    #pragma unroll
    for (int r = 0; r < 4; ++r) {
      float rn = sRN[rowsel + r];
      #pragma unroll
      for (int jp = 0; jp < 4; ++jp) {
        float2 s = unpack2(acc[r][jp]);
        int code0 = cbase + jp * 2;
        float en0 = __ldg(&g_norms[layer * N_EMBED + code0]);
        float en1 = __ldg(&g_norms[layer * N_EMBED + code0 + 1]);
        float d0 = __fadd_rn(__fadd_rn(rn, __fmul_rn(-2.0f, s.x)), en0);
        float d1 = __fadd_rn(__fadd_rn(rn, __fmul_rn(-2.0f, s.y)), en1);
        if (d0 < bestv[r]) { bestv[r] = d0; besti[r] = code0; }
        if (d1 < bestv[r]) { bestv[r] = d1; besti[r] = code0 + 1; }
      }
    }
  }

  // in-warp argmin reduce across the 4 code-groups (lanes xor 8, 16)
  #pragma unroll
  for (int off = 8; off <= 16; off <<= 1) {
    #pragma unroll
    for (int r = 0; r < 4; ++r) {
      float ov = __shfl_xor_sync(0xffffffff, bestv[r], off);
      int   oi = __shfl_xor_sync(0xffffffff, besti[r], off);
      if (ov < bestv[r] || (ov == bestv[r] && oi < besti[r])) {
        bestv[r] = ov; besti[r] = oi;
      }
    }
  }
  if (cg == 0) {
    #pragma unroll
    for (int r = 0; r < 4; ++r) {
      sArgV[cq * TM + rowsel + r] = bestv[r];
      sArgI[cq * TM + rowsel + r] = besti[r];
    }
  }
  __syncthreads();

  // cross-warp argmin over the 4 code quarters
  if (tid < TM) {
    float bv = sArgV[tid];
    int   bi = sArgI[tid];
    #pragma unroll
    for (int q = 1; q < 4; ++q) {
      float v = sArgV[q * TM + tid];
      int   i = sArgI[q * TM + tid];
      if (v < bv || (v == bv && i < bi)) { bv = v; bi = i; }
    }
    sInd[tid] = bi;
  }
  __syncthreads();

  // ------------- epilogue: exact straight-through chain (residual from global) -------------
  float lsum = 0.f;
  const size_t rowbase = (size_t)blockIdx.x * TM;

  #pragma unroll 1
  for (int rr = 0; rr < 8; ++rr) {
    int r = wid * 8 + rr;
    int c = sInd[r];
    const float* q   = g_embT + ((size_t)layer * N_EMBED + c) * DIM;
    float* outp      = qout  + (rowbase + r) * DIM;
    float* resp      = g_res + (rowbase + r) * DIM;
    const float* rsm = rbase + r * DIM;
    #pragma unroll
    for (int h = 0; h < 2; ++h) {
      int d = lane * 4 + h * 128;
      float4 qv = __ldg((const float4*)(q + d));
      float4 rv = __ldg((const float4*)(rsm + d));
      float4 dq, qst, nr;
      dq.x = __fadd_rn(qv.x, -rv.x); dq.y = __fadd_rn(qv.y, -rv.y);
      dq.z = __fadd_rn(qv.z, -rv.z); dq.w = __fadd_rn(qv.w, -rv.w);
      qst.x = __fadd_rn(rv.x, dq.x); qst.y = __fadd_rn(rv.y, dq.y);
      qst.z = __fadd_rn(rv.z, dq.z); qst.w = __fadd_rn(rv.w, dq.w);
      nr.x = __fadd_rn(rv.x, -qst.x); nr.y = __fadd_rn(rv.y, -qst.y);
      nr.z = __fadd_rn(rv.z, -qst.z); nr.w = __fadd_rn(rv.w, -qst.w);
      *(float4*)(resp + d) = nr;
      float4 ov;
      if (layer == 0) {
        ov = qst;
      } else {
        ov = *(const float4*)(outp + d);
        ov.x = __fadd_rn(ov.x, qst.x); ov.y = __fadd_rn(ov.y, qst.y);
        ov.z = __fadd_rn(ov.z, qst.z); ov.w = __fadd_rn(ov.w, qst.w);
      }
      *(float4*)(outp + d) = ov;
      lsum += __fmul_rn(dq.x, dq.x) + __fmul_rn(dq.y, dq.y)
            + __fmul_rn(dq.z, dq.z) + __fmul_rn(dq.w, dq.w);
    }
    if (lane == 0) atomicAdd(&g_counts[layer * N_EMBED + c], 1);
  }

  #pragma unroll
  for (int off = 16; off > 0; off >>= 1)
    lsum += __shfl_xor_sync(0xffffffff, lsum, off);
  if (lane == 0) sRed[wid] = lsum;
  __syncthreads();
  if (tid == 0) {
    float s = 0.f;
    #pragma unroll
    for (int w = 0; w < 8; ++w) s += sRed[w];
    g_losspart[layer * (NROWS / TM) + blockIdx.x] = s;
  }
}

// ---------------- finalize: loss mean + perplexity ----------------
__global__ void finalize_kernel(float* __restrict__ out) {
  const int l = blockIdx.x;
  const int tid = threadIdx.x;
  __shared__ double sd[256];
  __shared__ float  sf[256];
  double ls = 0.0;
  float  es = 0.f;
  for (int i = tid; i < NROWS / TM; i += 256)
    ls += (double)g_losspart[l * (NROWS / TM) + i];
  for (int i = tid; i < N_EMBED; i += 256) {
    float p = (float)g_counts[l * N_EMBED + i] * (1.0f / (float)NROWS);
    es += p * logf(__fadd_rn(p, 1e-10f));
  }
  sd[tid] = ls; sf[tid] = es;
  __syncthreads();
  for (int s = 128; s > 0; s >>= 1) {
    if (tid < s) { sd[tid] += sd[tid + s]; sf[tid] += sf[tid + s]; }
    __syncthreads();
  }
  if (tid == 0) {
    out[QOUT_ELEMS + l]         = (float)(sd[0] / (double)QOUT_ELEMS);
    out[QOUT_ELEMS + NUM_Q + l] = expf(-sf[0]);
  }
}

extern "C" void kernel_launch(void* const* d_in, const int* in_sizes, int n_in,
                              void* d_out, int out_size) {
  const float* x      = (const float*)d_in[0];
  const float* embeds = (const float*)d_in[1];
  float* out          = (float*)d_out;

  const int smem_bytes =
      (DIM * ATS + BK * BSROW + TM + TM + 8 + 4 * TM + 4 * TM) * 4;
  cudaFuncSetAttribute(vq_layer_kernel,
                       cudaFuncAttributeMaxDynamicSharedMemorySize, smem_bytes);

  prep_kernel<<<(NUM_Q * N_EMBED * DIM) / 256, 256>>>(embeds);
  norms_kernel<<<(NUM_Q * N_EMBED) / 256, 256>>>(embeds);

  for (int l = 0; l < NUM_Q; ++l) {
    vq_layer_kernel<<<NROWS / TM, NTHREADS, smem_bytes>>>(x, embeds, out, l);
  }
  finalize_kernel<<<NUM_Q, 256>>>(out);
}

// round 7
// speedup vs baseline: 2.8821x; 1.0349x over previous
#include <cuda_runtime.h>
#include <math.h>

#define NUM_Q   8
#define DIM     256
#define N_EMBED 1024
#define NROWS   65536
#define QOUT_ELEMS (NROWS * DIM)

#define TM 64       // rows per block
#define TNC 128     // codes per ct tile
#define BK 32       // k-chunk
#define NTHREADS 256
#define ATS 68      // At row stride (floats)
#define BSROW 132   // Bs row stride (floats): 128 + 4 pad
#define NCHUNK (N_EMBED / TNC * DIM / BK)   // 64 chunks per layer pass

__device__ float g_res[NROWS * DIM];
__device__ float g_embT[NUM_Q * N_EMBED * DIM];
__device__ float g_norms[NUM_Q * N_EMBED];
__device__ float g_losspart[NUM_Q * (NROWS / TM)];
__device__ int   g_counts[NUM_Q * N_EMBED];

typedef unsigned long long ull;
__device__ __forceinline__ ull fma2(ull a, ull b, ull c) {
  ull d; asm("fma.rn.f32x2 %0, %1, %2, %3;" : "=l"(d) : "l"(a), "l"(b), "l"(c));
  return d;
}
__device__ __forceinline__ ull packdup(float x) {
  ull r; asm("mov.b64 %0, {%1, %1};" : "=l"(r) : "f"(x));
  return r;
}
__device__ __forceinline__ float2 unpack2(ull v) {
  float2 f; asm("mov.b64 {%0, %1}, %2;" : "=f"(f.x), "=f"(f.y) : "l"(v));
  return f;
}

// ---------------- prep: transpose codebooks (code-major) + zero counts ----------------
__global__ void prep_kernel(const float* __restrict__ embeds) {
  int idx = blockIdx.x * 256 + threadIdx.x;
  int l = idx >> 18;
  int rem = idx & 262143;
  int d = rem >> 10;
  int k = rem & 1023;
  g_embT[((size_t)l * N_EMBED + k) * DIM + d] = embeds[idx];
  if (idx < NUM_Q * N_EMBED) g_counts[idx] = 0;
}

// ---------------- code norms: sequential d, separate mul+add ----------------
__global__ void norms_kernel(const float* __restrict__ embeds) {
  int k = blockIdx.x * 256 + threadIdx.x;
  int l = k >> 10;
  int kk = k & 1023;
  float s = 0.f;
  for (int d = 0; d < DIM; ++d) {
    float v = embeds[((size_t)l * DIM + d) * N_EMBED + kk];
    s = __fadd_rn(s, __fmul_rn(v, v));
  }
  g_norms[k] = s;
}

// ---------------- main fused VQ layer ----------------
__global__ void __launch_bounds__(NTHREADS, 2)
vq_layer_kernel(const float* __restrict__ x,
                const float* __restrict__ embeds,
                float* __restrict__ qout,
                int layer) {
  extern __shared__ float sm[];
  float* At    = sm;                           // [DIM][ATS] transposed residual
  float* Bs    = At + DIM * ATS;               // [2][BK][BSROW] double-buffered
  float* sRN   = Bs + 2 * BK * BSROW;          // [TM]
  int*   sInd  = (int*)(sRN + TM);             // [TM]
  float* sRed  = (float*)(sInd + TM);          // [8]
  float* sArgV = sRed + 8;                     // [4][TM]
  int*   sArgI = (int*)(sArgV + 4 * TM);       // [4][TM]

  const int tid = threadIdx.x;
  const int wid = tid >> 5, lane = tid & 31;
  const int rhalf = wid & 1;            // row half (0/1)
  const int cq    = wid >> 1;           // code quarter (0..3)
  const int rg    = lane & 7;           // row group within half
  const int cg    = lane >> 3;          // code group within quarter
  const int rowsel  = rhalf * 32 + rg * 4;
  const int codesel = cq * 32 + cg * 8;

  const float* resin = (layer == 0) ? x : g_res;
  const float* rbase = resin + (size_t)blockIdx.x * TM * DIM;

  // ---- ||r||^2 per row (XLA row-reduce pattern, from global) ----
  #pragma unroll 1
  for (int rr = 0; rr < 8; ++rr) {
    int row = wid * 8 + rr;
    const float* rp = rbase + row * DIM;
    float p0 = 0.f, p1 = 0.f;
    #pragma unroll
    for (int i = 0; i < 4; ++i) {
      float2 v = __ldg((const float2*)&rp[i * 64 + 2 * lane]);
      p0 = __fadd_rn(p0, __fmul_rn(v.x, v.x));
      p1 = __fadd_rn(p1, __fmul_rn(v.y, v.y));
    }
    float a = __fadd_rn(p0, p1);
    #pragma unroll
    for (int off = 16; off > 0; off >>= 1)
      a = __fadd_rn(a, __shfl_down_sync(0xffffffff, a, off));
    if (lane == 0) sRN[row] = a;
  }

  // ---- scatter-store transposed residual: At[d][row] ----
  {
    const int row = tid & 63;
    const int g0  = tid >> 6;
    const float* rp = rbase + row * DIM;
    #pragma unroll
    for (int g = 0; g < 16; ++g) {
      int gg = g0 + g * 4;
      float4 v = __ldg((const float4*)rp + gg);
      At[(gg * 4 + 0) * ATS + row] = v.x;
      At[(gg * 4 + 1) * ATS + row] = v.y;
      At[(gg * 4 + 2) * ATS + row] = v.z;
      At[(gg * 4 + 3) * ATS + row] = v.w;
    }
  }

  // B-fill assignment: thread loads 16 consecutive floats of one k-row
  const int brow = tid >> 3;          // 0..31
  const int bcol = (tid & 7) * 16;    // 0..112

  // chunk address helper (chunk idx = ct*8 + kc)
  auto bsrc = [&](int idx) {
    int ict = idx >> 3, ikc = idx & 7;
    return embeds + ((size_t)(layer * DIM + ikc * BK + brow)) * N_EMBED
           + ict * TNC + bcol;
  };

  // prologue: chunk0 -> buf0 directly; LDG chunk1 into regs
  float4 nv0, nv1, nv2, nv3;
  {
    const float* g = bsrc(0);
    float4 v0 = __ldg((const float4*)g);
    float4 v1 = __ldg((const float4*)g + 1);
    float4 v2 = __ldg((const float4*)g + 2);
    float4 v3 = __ldg((const float4*)g + 3);
    float* bd = Bs + brow * BSROW + bcol;
    *(float4*)(bd + 0)  = v0;
    *(float4*)(bd + 4)  = v1;
    *(float4*)(bd + 8)  = v2;
    *(float4*)(bd + 12) = v3;
    const float* g1 = bsrc(1);
    nv0 = __ldg((const float4*)g1);
    nv1 = __ldg((const float4*)g1 + 1);
    nv2 = __ldg((const float4*)g1 + 2);
    nv3 = __ldg((const float4*)g1 + 3);
  }
  __syncthreads();

  float bestv[4];
  int   besti[4];
  #pragma unroll
  for (int i = 0; i < 4; ++i) { bestv[i] = 3.4028235e38f; besti[i] = 0; }

  for (int ct = 0; ct < N_EMBED / TNC; ++ct) {
    ull acc[4][4];
    #pragma unroll
    for (int r = 0; r < 4; ++r)
      #pragma unroll
      for (int j = 0; j < 4; ++j) acc[r][j] = 0ull;

    for (int kc = 0; kc < DIM / BK; ++kc) {
      const int idx = ct * 8 + kc;
      const int p = idx & 1;

      // store prefetched chunk idx+1 into the other buffer
      if (idx + 1 < NCHUNK) {
        float* bd = Bs + (p ^ 1) * (BK * BSROW) + brow * BSROW + bcol;
        *(float4*)(bd + 0)  = nv0;
        *(float4*)(bd + 4)  = nv1;
        *(float4*)(bd + 8)  = nv2;
        *(float4*)(bd + 12) = nv3;
      }
      // LDG chunk idx+2
      if (idx + 2 < NCHUNK) {
        const float* g = bsrc(idx + 2);
        nv0 = __ldg((const float4*)g);
        nv1 = __ldg((const float4*)g + 1);
        nv2 = __ldg((const float4*)g + 2);
        nv3 = __ldg((const float4*)g + 3);
      }

      // compute on buffer p, software-pipelined LDS
      const float* apd = At + (kc * BK) * ATS + rowsel;
      const float* bpd = Bs + p * (BK * BSROW) + codesel;
      float4 a_c = *(const float4*)apd;
      ulonglong2 b01_c = *(const ulonglong2*)bpd;
      ulonglong2 b23_c = *(const ulonglong2*)(bpd + 4);
      #pragma unroll
      for (int d = 0; d < BK; ++d) {
        float4 a_n;
        ulonglong2 b01_n, b23_n;
        if (d + 1 < BK) {
          a_n   = *(const float4*)(apd + (d + 1) * ATS);
          b01_n = *(const ulonglong2*)(bpd + (d + 1) * BSROW);
          b23_n = *(const ulonglong2*)(bpd + (d + 1) * BSROW + 4);
        }
        ull ad0 = packdup(a_c.x), ad1 = packdup(a_c.y);
        ull ad2 = packdup(a_c.z), ad3 = packdup(a_c.w);
        acc[0][0] = fma2(ad0, b01_c.x, acc[0][0]);
        acc[0][1] = fma2(ad0, b01_c.y, acc[0][1]);
        acc[0][2] = fma2(ad0, b23_c.x, acc[0][2]);
        acc[0][3] = fma2(ad0, b23_c.y, acc[0][3]);
        acc[1][0] = fma2(ad1, b01_c.x, acc[1][0]);
        acc[1][1] = fma2(ad1, b01_c.y, acc[1][1]);
        acc[1][2] = fma2(ad1, b23_c.x, acc[1][2]);
        acc[1][3] = fma2(ad1, b23_c.y, acc[1][3]);
        acc[2][0] = fma2(ad2, b01_c.x, acc[2][0]);
        acc[2][1] = fma2(ad2, b01_c.y, acc[2][1]);
        acc[2][2] = fma2(ad2, b23_c.x, acc[2][2]);
        acc[2][3] = fma2(ad2, b23_c.y, acc[2][3]);
        acc[3][0] = fma2(ad3, b01_c.x, acc[3][0]);
        acc[3][1] = fma2(ad3, b01_c.y, acc[3][1]);
        acc[3][2] = fma2(ad3, b23_c.x, acc[3][2]);
        acc[3][3] = fma2(ad3, b23_c.y, acc[3][3]);
        a_c = a_n; b01_c = b01_n; b23_c = b23_n;
      }
      __syncthreads();   // one barrier per chunk
    }

    // dist = (rn - 2*ab) + en, exact association, ascending code order
    const int cbase = ct * TNC + codesel;
    #pragma unroll
    for (int r = 0; r < 4; ++r) {
      float rn = sRN[rowsel + r];
      #pragma unroll
      for (int jp = 0; jp < 4; ++jp) {
        float2 s = unpack2(acc[r][jp]);
        int code0 = cbase + jp * 2;
        float en0 = __ldg(&g_norms[layer * N_EMBED + code0]);
        float en1 = __ldg(&g_norms[layer * N_EMBED + code0 + 1]);
        float d0 = __fadd_rn(__fadd_rn(rn, __fmul_rn(-2.0f, s.x)), en0);
        float d1 = __fadd_rn(__fadd_rn(rn, __fmul_rn(-2.0f, s.y)), en1);
        if (d0 < bestv[r]) { bestv[r] = d0; besti[r] = code0; }
        if (d1 < bestv[r]) { bestv[r] = d1; besti[r] = code0 + 1; }
      }
    }
  }

  // in-warp argmin reduce across the 4 code-groups (lanes xor 8, 16)
  #pragma unroll
  for (int off = 8; off <= 16; off <<= 1) {
    #pragma unroll
    for (int r = 0; r < 4; ++r) {
      float ov = __shfl_xor_sync(0xffffffff, bestv[r], off);
      int   oi = __shfl_xor_sync(0xffffffff, besti[r], off);
      if (ov < bestv[r] || (ov == bestv[r] && oi < besti[r])) {
        bestv[r] = ov; besti[r] = oi;
      }
    }
  }
  if (cg == 0) {
    #pragma unroll
    for (int r = 0; r < 4; ++r) {
      sArgV[cq * TM + rowsel + r] = bestv[r];
      sArgI[cq * TM + rowsel + r] = besti[r];
    }
  }
  __syncthreads();

  // cross-warp argmin over the 4 code quarters
  if (tid < TM) {
    float bv = sArgV[tid];
    int   bi = sArgI[tid];
    #pragma unroll
    for (int q = 1; q < 4; ++q) {
      float v = sArgV[q * TM + tid];
      int   i = sArgI[q * TM + tid];
      if (v < bv || (v == bv && i < bi)) { bv = v; bi = i; }
    }
    sInd[tid] = bi;
  }
  __syncthreads();

  // ------------- epilogue: exact straight-through chain -------------
  float lsum = 0.f;
  const size_t rowbase = (size_t)blockIdx.x * TM;

  #pragma unroll 1
  for (int rr = 0; rr < 8; ++rr) {
    int r = wid * 8 + rr;
    int c = sInd[r];
    const float* q   = g_embT + ((size_t)layer * N_EMBED + c) * DIM;
    float* outp      = qout  + (rowbase + r) * DIM;
    float* resp      = g_res + (rowbase + r) * DIM;
    const float* rsm = rbase + r * DIM;
    #pragma unroll
    for (int h = 0; h < 2; ++h) {
      int d = lane * 4 + h * 128;
      float4 qv = __ldg((const float4*)(q + d));
      float4 rv = __ldg((const float4*)(rsm + d));
      float4 dq, qst, nr;
      dq.x = __fadd_rn(qv.x, -rv.x); dq.y = __fadd_rn(qv.y, -rv.y);
      dq.z = __fadd_rn(qv.z, -rv.z); dq.w = __fadd_rn(qv.w, -rv.w);
      qst.x = __fadd_rn(rv.x, dq.x); qst.y = __fadd_rn(rv.y, dq.y);
      qst.z = __fadd_rn(rv.z, dq.z); qst.w = __fadd_rn(rv.w, dq.w);
      nr.x = __fadd_rn(rv.x, -qst.x); nr.y = __fadd_rn(rv.y, -qst.y);
      nr.z = __fadd_rn(rv.z, -qst.z); nr.w = __fadd_rn(rv.w, -qst.w);
      *(float4*)(resp + d) = nr;
      float4 ov;
      if (layer == 0) {
        ov = qst;
      } else {
        ov = *(const float4*)(outp + d);
        ov.x = __fadd_rn(ov.x, qst.x); ov.y = __fadd_rn(ov.y, qst.y);
        ov.z = __fadd_rn(ov.z, qst.z); ov.w = __fadd_rn(ov.w, qst.w);
      }
      *(float4*)(outp + d) = ov;
      lsum += __fmul_rn(dq.x, dq.x) + __fmul_rn(dq.y, dq.y)
            + __fmul_rn(dq.z, dq.z) + __fmul_rn(dq.w, dq.w);
    }
    if (lane == 0) atomicAdd(&g_counts[layer * N_EMBED + c], 1);
  }

  #pragma unroll
  for (int off = 16; off > 0; off >>= 1)
    lsum += __shfl_xor_sync(0xffffffff, lsum, off);
  if (lane == 0) sRed[wid] = lsum;
  __syncthreads();
  if (tid == 0) {
    float s = 0.f;
    #pragma unroll
    for (int w = 0; w < 8; ++w) s += sRed[w];
    g_losspart[layer * (NROWS / TM) + blockIdx.x] = s;
  }
}

// ---------------- finalize: loss mean + perplexity ----------------
__global__ void finalize_kernel(float* __restrict__ out) {
  const int l = blockIdx.x;
  const int tid = threadIdx.x;
  __shared__ double sd[256];
  __shared__ float  sf[256];
  double ls = 0.0;
  float  es = 0.f;
  for (int i = tid; i < NROWS / TM; i += 256)
    ls += (double)g_losspart[l * (NROWS / TM) + i];
  for (int i = tid; i < N_EMBED; i += 256) {
    float p = (float)g_counts[l * N_EMBED + i] * (1.0f / (float)NROWS);
    es += p * logf(__fadd_rn(p, 1e-10f));
  }
  sd[tid] = ls; sf[tid] = es;
  __syncthreads();
  for (int s = 128; s > 0; s >>= 1) {
    if (tid < s) { sd[tid] += sd[tid + s]; sf[tid] += sf[tid + s]; }
    __syncthreads();
  }
  if (tid == 0) {
    out[QOUT_ELEMS + l]         = (float)(sd[0] / (double)QOUT_ELEMS);
    out[QOUT_ELEMS + NUM_Q + l] = expf(-sf[0]);
  }
}

extern "C" void kernel_launch(void* const* d_in, const int* in_sizes, int n_in,
                              void* d_out, int out_size) {
  const float* x      = (const float*)d_in[0];
  const float* embeds = (const float*)d_in[1];
  float* out          = (float*)d_out;

  const int smem_bytes =
      (DIM * ATS + 2 * BK * BSROW + TM + TM + 8 + 4 * TM + 4 * TM) * 4;
  cudaFuncSetAttribute(vq_layer_kernel,
                       cudaFuncAttributeMaxDynamicSharedMemorySize, smem_bytes);

  prep_kernel<<<(NUM_Q * N_EMBED * DIM) / 256, 256>>>(embeds);
  norms_kernel<<<(NUM_Q * N_EMBED) / 256, 256>>>(embeds);

  for (int l = 0; l < NUM_Q; ++l) {
    vq_layer_kernel<<<NROWS / TM, NTHREADS, smem_bytes>>>(x, embeds, out, l);
  }
  finalize_kernel<<<NUM_Q, 256>>>(out);
}